// round 3
// baseline (speedup 1.0000x reference)
#include <cuda_runtime.h>
#include <cuda_bf16.h>
#include <math.h>

// ---------------- Problem constants ----------------
constexpr int B   = 2;
constexpr int S   = 2048;
constexpr int D   = 2560;
constexpr int H   = 8;
constexpr int HKV = 4;
constexpr int HD  = 256;
constexpr int NTOK = B * S;                 // 4096
constexpr int QKV_COLS = H*HD + 2*HKV*HD;   // 4096 (q:0..2047, k:2048..3071, v:3072..4095)
constexpr float EPS = 1e-6f;
constexpr float SCALING = 0.0625f;          // 256^-0.5
constexpr float SOFTCAP = 4096.0f;
constexpr float NEGBIG = -1e9f;

// ---------------- Scratch (device globals; no allocation allowed) ----------------
__device__ float g_qkv[(size_t)NTOK * QKV_COLS];        // [token][4096]
__device__ float g_q[(size_t)B * H   * S * HD];         // [b][h][s][d]
__device__ float g_k[(size_t)B * HKV * S * HD];         // [b][hk][s][d]
__device__ float g_v[(size_t)B * HKV * S * HD];         // [b][hk][s][d]
__device__ float g_attn[(size_t)NTOK * (H*HD)];         // [token][h*HD + d]

// ---------------- Generic SGEMM:  C[m][coff+n] = sum_k A[m][k] * W[n][k] ----------------
// Row-major A[M][K], W[N][K]. BM=128, BN=64, BK=16, 256 threads, 8x4 microtile.
__global__ __launch_bounds__(256) void sgemm_nt(
    const float* __restrict__ A, const float* __restrict__ W, float* __restrict__ C,
    int M, int N, int K, int ldc, int col_off)
{
    constexpr int BM = 128, BN = 64, BK = 16;
    __shared__ float As[BK][BM];
    __shared__ float Ws[BK][BN + 1];

    const int tid = threadIdx.x;
    const int tx = tid & 15;      // 0..15 -> 4 cols each
    const int ty = tid >> 4;      // 0..15 -> 8 rows each
    const int m0 = blockIdx.y * BM;
    const int n0 = blockIdx.x * BN;

    float acc[8][4];
#pragma unroll
    for (int i = 0; i < 8; i++)
#pragma unroll
        for (int j = 0; j < 4; j++) acc[i][j] = 0.f;

    for (int k0 = 0; k0 < K; k0 += BK) {
        // Load A tile: 128x16 = 512 float4; i4 = t*256 + tid -> coalesced
#pragma unroll
        for (int t = 0; t < 2; t++) {
            int i4  = t * 256 + tid;
            int row = i4 >> 2;
            int c4  = i4 & 3;
            float4 v = *(const float4*)(A + (size_t)(m0 + row) * K + k0 + c4 * 4);
            As[c4*4 + 0][row] = v.x; As[c4*4 + 1][row] = v.y;
            As[c4*4 + 2][row] = v.z; As[c4*4 + 3][row] = v.w;
        }
        // Load W tile: 64x16 = 256 float4
        {
            int row = tid >> 2;
            int c4  = tid & 3;
            float4 v = *(const float4*)(W + (size_t)(n0 + row) * K + k0 + c4 * 4);
            Ws[c4*4 + 0][row] = v.x; Ws[c4*4 + 1][row] = v.y;
            Ws[c4*4 + 2][row] = v.z; Ws[c4*4 + 3][row] = v.w;
        }
        __syncthreads();

#pragma unroll
        for (int kk = 0; kk < BK; kk++) {
            float a[8], bb[4];
            float4 a0 = *(const float4*)(&As[kk][ty * 8]);
            float4 a1 = *(const float4*)(&As[kk][ty * 8 + 4]);
            a[0]=a0.x; a[1]=a0.y; a[2]=a0.z; a[3]=a0.w;
            a[4]=a1.x; a[5]=a1.y; a[6]=a1.z; a[7]=a1.w;
#pragma unroll
            for (int j = 0; j < 4; j++) bb[j] = Ws[kk][tx * 4 + j];
#pragma unroll
            for (int i = 0; i < 8; i++)
#pragma unroll
                for (int j = 0; j < 4; j++)
                    acc[i][j] = fmaf(a[i], bb[j], acc[i][j]);
        }
        __syncthreads();
    }

#pragma unroll
    for (int i = 0; i < 8; i++) {
        float* crow = C + (size_t)(m0 + ty * 8 + i) * ldc + col_off + n0 + tx * 4;
#pragma unroll
        for (int j = 0; j < 4; j++) crow[j] = acc[i][j];
    }
}

// ---------------- RMSNorm + RoPE + layout transform ----------------
// grid: (NTOK, 16).  slot 0..7 = q head; 8..11 = k head; 12..15 = v head (copy only).
__global__ __launch_bounds__(256) void norm_rope_kernel(
    const float* __restrict__ cosp, const float* __restrict__ sinp,
    const float* __restrict__ qn_w, const float* __restrict__ kn_w)
{
    const int token = blockIdx.x;
    const int slot  = blockIdx.y;
    const int d     = threadIdx.x;
    const int b = token / S;
    const int s = token % S;

    const float* row = g_qkv + (size_t)token * QKV_COLS;
    float x;
    if (slot < 8)       x = row[slot * HD + d];
    else if (slot < 12) x = row[2048 + (slot - 8) * HD + d];
    else                x = row[3072 + (slot - 12) * HD + d];

    if (slot >= 12) {
        g_v[(((size_t)b * HKV + (slot - 12)) * S + s) * HD + d] = x;
        return;
    }

    // block-reduce sum of squares over 256 lanes
    __shared__ float red[8];
    __shared__ float xs[HD];
    float ss = x * x;
#pragma unroll
    for (int o = 16; o > 0; o >>= 1) ss += __shfl_xor_sync(0xffffffffu, ss, o);
    if ((d & 31) == 0) red[d >> 5] = ss;
    __syncthreads();
    float tot = red[0];
#pragma unroll
    for (int i = 1; i < 8; i++) tot += red[i];
    const float scale = rsqrtf(tot * (1.0f / HD) + EPS);

    const float* nw = (slot < 8) ? qn_w : kn_w;
    const float xn = x * scale * (1.0f + nw[d]);
    xs[d] = xn;
    __syncthreads();

    const float rot = (d < HD/2) ? -xs[d + HD/2] : xs[d - HD/2];
    const size_t csi = ((size_t)b * S + s) * HD + d;
    const float out = xn * cosp[csi] + rot * sinp[csi];

    if (slot < 8)
        g_q[(((size_t)b * H + slot) * S + s) * HD + d] = out;
    else
        g_k[(((size_t)b * HKV + (slot - 8)) * S + s) * HD + d] = out;
}

// ---------------- Flash attention (fp32, causal, tanh softcap) ----------------
// BM = BN = 32, 256 threads. 8 threads per q-row (group g=tid&7).
// Row stride padded to 260 floats for conflict-free LDS128.
constexpr int PAD = 260;
constexpr int FLASH_SMEM = (3 * 32 * PAD + 32 * 33) * 4;   // 104064 bytes

__global__ __launch_bounds__(256) void flash_kernel()
{
    extern __shared__ float smf[];
    float* Qs = smf;
    float* Ks = smf + 32 * PAD;
    float* Vs = smf + 2 * 32 * PAD;
    float* Ps = smf + 3 * 32 * PAD;   // [32][33]

    const int qt = blockIdx.x;        // q tile (0..63)
    const int h  = blockIdx.y;
    const int b  = blockIdx.z;
    const int q0 = qt * 32;
    const int hk = h >> 1;            // GQA rep=2: jnp.repeat -> kv head = h/2

    const int tid = threadIdx.x;
    const int r = tid >> 3;           // q row in tile
    const int g = tid & 7;            // group within row

    const float* Qg = g_q + (((size_t)b * H   + h ) * S + q0) * HD;
    const float* Kg = g_k + (((size_t)b * HKV + hk) * S) * HD;
    const float* Vg = g_v + (((size_t)b * HKV + hk) * S) * HD;

    // Load Q tile (32 x 256)
    for (int i4 = tid; i4 < 32 * 64; i4 += 256) {
        int row = i4 >> 6, c4 = i4 & 63;
        *(float4*)(Qs + row * PAD + c4 * 4) = *(const float4*)(Qg + (size_t)row * HD + c4 * 4);
    }

    float4 o[8];
#pragma unroll
    for (int i = 0; i < 8; i++) o[i] = make_float4(0.f, 0.f, 0.f, 0.f);
    float m = -1e30f, l = 0.f;

    const int qg = q0 + r;

    for (int kt = 0; kt <= qt; kt++) {
        __syncthreads();   // also fences Q load on first iteration
        const float* Kt = Kg + (size_t)kt * 32 * HD;
        const float* Vt = Vg + (size_t)kt * 32 * HD;
        for (int i4 = tid; i4 < 32 * 64; i4 += 256) {
            int row = i4 >> 6, c4 = i4 & 63;
            *(float4*)(Ks + row * PAD + c4 * 4) = *(const float4*)(Kt + (size_t)row * HD + c4 * 4);
            *(float4*)(Vs + row * PAD + c4 * 4) = *(const float4*)(Vt + (size_t)row * HD + c4 * 4);
        }
        __syncthreads();

        // ---- scores: this thread owns k-cols {g, g+8, g+16, g+24} (conflict-free banks) ----
        const float4* qrow = (const float4*)(Qs + r * PAD);
        const float4* k0p = (const float4*)(Ks + (g +  0) * PAD);
        const float4* k1p = (const float4*)(Ks + (g +  8) * PAD);
        const float4* k2p = (const float4*)(Ks + (g + 16) * PAD);
        const float4* k3p = (const float4*)(Ks + (g + 24) * PAD);
        float a0 = 0.f, a1 = 0.f, a2 = 0.f, a3 = 0.f;
#pragma unroll 4
        for (int d4 = 0; d4 < 64; d4++) {
            float4 q = qrow[d4];
            float4 kv;
            kv = k0p[d4]; a0 = fmaf(q.x,kv.x, fmaf(q.y,kv.y, fmaf(q.z,kv.z, fmaf(q.w,kv.w, a0))));
            kv = k1p[d4]; a1 = fmaf(q.x,kv.x, fmaf(q.y,kv.y, fmaf(q.z,kv.z, fmaf(q.w,kv.w, a1))));
            kv = k2p[d4]; a2 = fmaf(q.x,kv.x, fmaf(q.y,kv.y, fmaf(q.z,kv.z, fmaf(q.w,kv.w, a2))));
            kv = k3p[d4]; a3 = fmaf(q.x,kv.x, fmaf(q.y,kv.y, fmaf(q.z,kv.z, fmaf(q.w,kv.w, a3))));
        }
        float sc[4] = {a0, a1, a2, a3};
        float lm = -1e30f;
#pragma unroll
        for (int jj = 0; jj < 4; jj++) {
            float w = sc[jj] * SCALING;
            w = tanhf(w * (1.0f / SOFTCAP)) * SOFTCAP;
            int kg = kt * 32 + g + jj * 8;
            if (kg > qg) w = NEGBIG;
            sc[jj] = w;
            lm = fmaxf(lm, w);
        }
        lm = fmaxf(lm, __shfl_xor_sync(0xffffffffu, lm, 1));
        lm = fmaxf(lm, __shfl_xor_sync(0xffffffffu, lm, 2));
        lm = fmaxf(lm, __shfl_xor_sync(0xffffffffu, lm, 4));

        const float mn = fmaxf(m, lm);
        const float corr = __expf(m - mn);
        float psum = 0.f;
#pragma unroll
        for (int jj = 0; jj < 4; jj++) {
            float p = __expf(sc[jj] - mn);
            psum += p;
            Ps[r * 33 + g + jj * 8] = p;
        }
        psum += __shfl_xor_sync(0xffffffffu, psum, 1);
        psum += __shfl_xor_sync(0xffffffffu, psum, 2);
        psum += __shfl_xor_sync(0xffffffffu, psum, 4);
        l = l * corr + psum;
        m = mn;
#pragma unroll
        for (int i = 0; i < 8; i++) {
            o[i].x *= corr; o[i].y *= corr; o[i].z *= corr; o[i].w *= corr;
        }
        __syncwarp();

        // ---- PV: this thread owns dims d4 = i*8 + g  (conflict-free banks) ----
        const float* prow = Ps + r * 33;
        for (int j = 0; j < 32; j++) {
            const float p = prow[j];
            const float4* vrow = (const float4*)(Vs + j * PAD);
#pragma unroll
            for (int i = 0; i < 8; i++) {
                float4 vv = vrow[i * 8 + g];
                o[i].x = fmaf(p, vv.x, o[i].x);
                o[i].y = fmaf(p, vv.y, o[i].y);
                o[i].z = fmaf(p, vv.z, o[i].z);
                o[i].w = fmaf(p, vv.w, o[i].w);
            }
        }
    }

    const float inv = 1.0f / l;
    float* outp = g_attn + ((size_t)(b * S + q0 + r)) * (H * HD) + h * HD;
#pragma unroll
    for (int i = 0; i < 8; i++) {
        float4 v = o[i];
        v.x *= inv; v.y *= inv; v.z *= inv; v.w *= inv;
        *(float4*)(outp + (i * 8 + g) * 4) = v;
    }
}

// ---------------- Host launch ----------------
extern "C" void kernel_launch(void* const* d_in, const int* in_sizes, int n_in,
                              void* d_out, int out_size)
{
    const float* x    = (const float*)d_in[0];
    const float* cosp = (const float*)d_in[1];
    const float* sinp = (const float*)d_in[2];
    // d_in[3] = mask (causal; computed analytically in-kernel)
    const float* q_w  = (const float*)d_in[4];
    const float* k_w  = (const float*)d_in[5];
    const float* v_w  = (const float*)d_in[6];
    const float* o_w  = (const float*)d_in[7];
    const float* qn_w = (const float*)d_in[8];
    const float* kn_w = (const float*)d_in[9];
    float* out = (float*)d_out;

    void *p_qkv, *p_attn;
    cudaGetSymbolAddress(&p_qkv,  g_qkv);
    cudaGetSymbolAddress(&p_attn, g_attn);
    float* qkv  = (float*)p_qkv;
    float* attn = (float*)p_attn;

    cudaFuncSetAttribute(flash_kernel, cudaFuncAttributeMaxDynamicSharedMemorySize, FLASH_SMEM);

    // 1) QKV projections into combined buffer
    sgemm_nt<<<dim3((H*HD)/64,   NTOK/128), 256>>>(x, q_w, qkv, NTOK, H*HD,   D, QKV_COLS, 0);
    sgemm_nt<<<dim3((HKV*HD)/64, NTOK/128), 256>>>(x, k_w, qkv, NTOK, HKV*HD, D, QKV_COLS, 2048);
    sgemm_nt<<<dim3((HKV*HD)/64, NTOK/128), 256>>>(x, v_w, qkv, NTOK, HKV*HD, D, QKV_COLS, 3072);

    // 2) RMSNorm + RoPE + transpose to head-major
    norm_rope_kernel<<<dim3(NTOK, 16), 256>>>(cosp, sinp, qn_w, kn_w);

    // 3) Flash attention
    flash_kernel<<<dim3(S/32, H, B), 256, FLASH_SMEM>>>();

    // 4) Output projection
    sgemm_nt<<<dim3(D/64, NTOK/128), 256>>>(attn, o_w, out, NTOK, D, H*HD, D, 0);
}

// round 8
// speedup vs baseline: 1.0648x; 1.0648x over previous
#include <cuda_runtime.h>
#include <cuda_bf16.h>
#include <math.h>
#include <cstdint>

// ---------------- Problem constants ----------------
constexpr int B   = 2;
constexpr int S   = 2048;
constexpr int D   = 2560;
constexpr int H   = 8;
constexpr int HKV = 4;
constexpr int HD  = 256;
constexpr int NTOK = B * S;                 // 4096
constexpr int QKV_COLS = H*HD + 2*HKV*HD;   // 4096
constexpr float EPS = 1e-6f;
constexpr float SCALING = 0.0625f;
constexpr float SOFTCAP = 4096.0f;
constexpr float NEGBIG = -1e9f;

constexpr int K1 = D;          // 2560, QKV reduction
constexpr int K1C = 3 * K1;    // 7680 cat
constexpr int K2 = H * HD;     // 2048, O-proj reduction
constexpr int K2C = 3 * K2;    // 6144 cat

// ---------------- Scratch (device globals) ----------------
__device__ float g_qkv[(size_t)NTOK * QKV_COLS];
__device__ float g_q[(size_t)B * H   * S * HD];
__device__ float g_k[(size_t)B * HKV * S * HD];
__device__ float g_v[(size_t)B * HKV * S * HD];
__device__ float g_attn[(size_t)NTOK * (H*HD)];
__device__ __nv_bfloat16 g_xcat  [(size_t)NTOK * K1C];     // [hi|lo|hi]
__device__ __nv_bfloat16 g_wqkvc [(size_t)QKV_COLS * K1C]; // [hi|hi|lo]
__device__ __nv_bfloat16 g_acat  [(size_t)NTOK * K2C];     // [hi|lo|hi]
__device__ __nv_bfloat16 g_woc   [(size_t)D * K2C];        // [hi|hi|lo]

// ================= helpers =================
__device__ __forceinline__ uint32_t smem_to_u32(const void* p) {
    uint32_t a;
    asm("{ .reg .u64 t; cvta.to.shared.u64 t, %1; cvt.u32.u64 %0, t; }" : "=r"(a) : "l"(p));
    return a;
}
#define SWZ128(o) ((o) ^ (((o) >> 3) & 0x70))

__device__ __forceinline__ void cp16(uint32_t s, const void* g) {
    asm volatile("cp.async.cg.shared.global [%0], [%1], 16;\n" :: "r"(s), "l"(g));
}
#define CP_COMMIT() asm volatile("cp.async.commit_group;\n" ::: "memory")
template<int N> __device__ __forceinline__ void cp_wait() {
    asm volatile("cp.async.wait_group %0;\n" :: "n"(N) : "memory");
}

__device__ __forceinline__ void ldm_x4(uint32_t* r, uint32_t addr) {
    asm volatile("ldmatrix.sync.aligned.m8n8.x4.shared.b16 {%0,%1,%2,%3}, [%4];"
        : "=r"(r[0]), "=r"(r[1]), "=r"(r[2]), "=r"(r[3]) : "r"(addr));
}
__device__ __forceinline__ void mma_bf16(float* d, const uint32_t* a, uint32_t b0, uint32_t b1) {
    asm volatile("mma.sync.aligned.m16n8k16.row.col.f32.bf16.bf16.f32 "
        "{%0,%1,%2,%3}, {%4,%5,%6,%7}, {%8,%9}, {%0,%1,%2,%3};"
        : "+f"(d[0]), "+f"(d[1]), "+f"(d[2]), "+f"(d[3])
        : "r"(a[0]), "r"(a[1]), "r"(a[2]), "r"(a[3]), "r"(b0), "r"(b1));
}

// ================ Split-precision conversion kernels ================
__device__ __forceinline__ void split4(float4 v, __nv_bfloat16* h, __nv_bfloat16* l) {
    h[0] = __float2bfloat16(v.x); l[0] = __float2bfloat16(v.x - __bfloat162float(h[0]));
    h[1] = __float2bfloat16(v.y); l[1] = __float2bfloat16(v.y - __bfloat162float(h[1]));
    h[2] = __float2bfloat16(v.z); l[2] = __float2bfloat16(v.z - __bfloat162float(h[2]));
    h[3] = __float2bfloat16(v.w); l[3] = __float2bfloat16(v.w - __bfloat162float(h[3]));
}
__device__ __forceinline__ void st8(__nv_bfloat16* p, const __nv_bfloat16* v) {
    *(uint2*)p = *(const uint2*)v;
}

// mode 0 (activation): [hi | lo | hi]; mode 1 (weight): [hi | hi | lo]
__global__ __launch_bounds__(256) void conv_cat(const float* __restrict__ src,
                                                __nv_bfloat16* __restrict__ dst,
                                                int K, long tot, int mode)
{
    long idx = (long)blockIdx.x * 256 + threadIdx.x;
    if (idx >= tot) return;
    int kq = K >> 2;
    long r = idx / kq; int k4 = (int)(idx - r * kq);
    float4 v = ((const float4*)src)[idx];
    __nv_bfloat16 h[4], l[4];
    split4(v, h, l);
    __nv_bfloat16* row = dst + r * (long)(3 * K);
    st8(row + k4 * 4, h);
    st8(row + K + k4 * 4, mode ? h : l);
    st8(row + 2 * K + k4 * 4, mode ? l : h);
}

__global__ __launch_bounds__(256) void conv_cat_qkv(const float* __restrict__ qw,
                                                    const float* __restrict__ kw,
                                                    const float* __restrict__ vw,
                                                    __nv_bfloat16* __restrict__ dst)
{
    const int K = K1, kq = K >> 2;
    long idx = (long)blockIdx.x * 256 + threadIdx.x;
    long tot = (long)QKV_COLS * kq;
    if (idx >= tot) return;
    long r = idx / kq; int k4 = (int)(idx - r * kq);
    const float* src = (r < 2048) ? qw + r * (long)K
                     : (r < 3072) ? kw + (r - 2048) * (long)K
                                  : vw + (r - 3072) * (long)K;
    float4 v = ((const float4*)src)[k4];
    __nv_bfloat16 h[4], l[4];
    split4(v, h, l);
    __nv_bfloat16* row = dst + r * (long)(3 * K);
    st8(row + k4 * 4, h);
    st8(row + K + k4 * 4, h);     // weight: hi | hi | lo
    st8(row + 2 * K + k4 * 4, l);
}

// ================ bf16 HMMA GEMM (mma.sync, base-ISA safe) ================
// C[m0+128][n0+128] = sum_k A[m][k] * Bw[n][k]; A/Bw bf16 row-major Kp cols; C fp32.
// 8 warps, 2(m) x 4(n), warp tile 64x32, m16n8k16 frags 4x4. BK=64 per chunk.
constexpr int STAGE_BYTES = 32768;       // A 16KB + B 16KB (128 rows x 128B each)
constexpr int NSTAGE = 3;
constexpr int GEMM_SMEM = NSTAGE * STAGE_BYTES;   // 98304

__device__ __forceinline__ void load_chunk(const char* Arow, const char* Brow, size_t rowbytes,
                                           uint32_t smem_base, int stage, long kbyte, int tid)
{
    uint32_t sa = smem_base + stage * STAGE_BYTES;
    uint32_t sb = sa + 16384;
#pragma unroll
    for (int p = 0; p < 4; p++) {
        int idx = p * 256 + tid;
        int row = idx >> 3, j = idx & 7;
        uint32_t off = (uint32_t)(row * 128 + j * 16);
        cp16(sa + SWZ128(off), Arow + (size_t)row * rowbytes + kbyte + j * 16);
    }
#pragma unroll
    for (int p = 0; p < 4; p++) {
        int idx = p * 256 + tid;
        int row = idx >> 3, j = idx & 7;
        uint32_t off = (uint32_t)(row * 128 + j * 16);
        cp16(sb + SWZ128(off), Brow + (size_t)row * rowbytes + kbyte + j * 16);
    }
    CP_COMMIT();
}

__global__ __launch_bounds__(256) void gemm_bf16(const __nv_bfloat16* __restrict__ A,
                                                 const __nv_bfloat16* __restrict__ Bw,
                                                 float* __restrict__ C,
                                                 int Kp, int Ntot)
{
    extern __shared__ char smem[];
    const uint32_t smem_base = smem_to_u32(smem);
    const int tid = threadIdx.x;
    const int wid = tid >> 5, lane = tid & 31;
    const int wm = wid & 1;          // 0..1 : 64-row slab
    const int wn = wid >> 1;         // 0..3 : 32-col slab
    const int n0 = blockIdx.x * 128;
    const int m0 = blockIdx.y * 128;

    const size_t rowbytes = (size_t)Kp * 2;
    const char* Arow = (const char*)A + (size_t)m0 * rowbytes;
    const char* Brow = (const char*)Bw + (size_t)n0 * rowbytes;
    const int C_chunks = Kp / 64;

    load_chunk(Arow, Brow, rowbytes, smem_base, 0, 0, tid);
    load_chunk(Arow, Brow, rowbytes, smem_base, 1, 128, tid);
    load_chunk(Arow, Brow, rowbytes, smem_base, 2, 256, tid);

    float acc[4][4][4];
#pragma unroll
    for (int i = 0; i < 4; i++)
#pragma unroll
        for (int j = 0; j < 4; j++)
#pragma unroll
            for (int q = 0; q < 4; q++) acc[i][j][q] = 0.f;

    // Precompute per-lane ldmatrix row/col components.
    // A: m = wm*64 + mf*16 + (lane&15); k-half select = lane>>4 (16B)
    const int a_row_l = (lane & 15);
    const int a_hi    = (lane >> 4) * 16;
    // B: n = wn*32 + nb*16 + (lane&7) + ((lane>>4)&1)*8; k-half = ((lane>>3)&1)*16
    const int b_row_l = (lane & 7) + ((lane >> 4) & 1) * 8;
    const int b_hi    = ((lane >> 3) & 1) * 16;

    for (int c = 0; c < C_chunks; c++) {
        const int s = c % 3;
        if (c + 2 < C_chunks)      cp_wait<2>();
        else if (c + 1 < C_chunks) cp_wait<1>();
        else                       cp_wait<0>();
        __syncthreads();

        const uint32_t sa = smem_base + s * STAGE_BYTES;
        const uint32_t sb = sa + 16384;

#pragma unroll
        for (int ks = 0; ks < 4; ks++) {
            uint32_t a[4][4];
#pragma unroll
            for (int mf = 0; mf < 4; mf++) {
                int row = wm * 64 + mf * 16 + a_row_l;
                uint32_t kb = (uint32_t)(ks * 32 + a_hi) ^ ((uint32_t)(row & 7) << 4);
                ldm_x4(a[mf], sa + row * 128 + kb);
            }
            uint32_t bfr[2][4];
#pragma unroll
            for (int nb = 0; nb < 2; nb++) {
                int row = wn * 32 + nb * 16 + b_row_l;
                uint32_t kb = (uint32_t)(ks * 32 + b_hi) ^ ((uint32_t)(row & 7) << 4);
                ldm_x4(bfr[nb], sb + row * 128 + kb);
            }
#pragma unroll
            for (int mf = 0; mf < 4; mf++) {
#pragma unroll
                for (int nf = 0; nf < 4; nf++)
                    mma_bf16(acc[mf][nf], a[mf], bfr[nf >> 1][(nf & 1) * 2], bfr[nf >> 1][(nf & 1) * 2 + 1]);
            }
        }
        __syncthreads();
        if (c + 3 < C_chunks)
            load_chunk(Arow, Brow, rowbytes, smem_base, s, (long)(c + 3) * 128, tid);
    }

    // Epilogue: direct stores. Thread t of frag: rows t/4 and t/4+8, cols 2*(t%4).
    const int er = lane >> 2;
    const int ec = (lane & 3) * 2;
#pragma unroll
    for (int mf = 0; mf < 4; mf++) {
        const int rbase = m0 + wm * 64 + mf * 16 + er;
#pragma unroll
        for (int nf = 0; nf < 4; nf++) {
            const int cbase = n0 + wn * 32 + nf * 8 + ec;
            float* p0 = C + (size_t)rbase * Ntot + cbase;
            float* p1 = C + (size_t)(rbase + 8) * Ntot + cbase;
            *(float2*)p0 = make_float2(acc[mf][nf][0], acc[mf][nf][1]);
            *(float2*)p1 = make_float2(acc[mf][nf][2], acc[mf][nf][3]);
        }
    }
}

// ---------------- RMSNorm + RoPE + layout transform (unchanged) ----------------
__global__ __launch_bounds__(256) void norm_rope_kernel(
    const float* __restrict__ cosp, const float* __restrict__ sinp,
    const float* __restrict__ qn_w, const float* __restrict__ kn_w)
{
    const int token = blockIdx.x;
    const int slot  = blockIdx.y;
    const int d     = threadIdx.x;
    const int b = token / S;
    const int s = token % S;

    const float* row = g_qkv + (size_t)token * QKV_COLS;
    float x;
    if (slot < 8)       x = row[slot * HD + d];
    else if (slot < 12) x = row[2048 + (slot - 8) * HD + d];
    else                x = row[3072 + (slot - 12) * HD + d];

    if (slot >= 12) {
        g_v[(((size_t)b * HKV + (slot - 12)) * S + s) * HD + d] = x;
        return;
    }

    __shared__ float red[8];
    __shared__ float xs[HD];
    float ss = x * x;
#pragma unroll
    for (int o = 16; o > 0; o >>= 1) ss += __shfl_xor_sync(0xffffffffu, ss, o);
    if ((d & 31) == 0) red[d >> 5] = ss;
    __syncthreads();
    float tot = red[0];
#pragma unroll
    for (int i = 1; i < 8; i++) tot += red[i];
    const float scale = rsqrtf(tot * (1.0f / HD) + EPS);

    const float* nw = (slot < 8) ? qn_w : kn_w;
    const float xn = x * scale * (1.0f + nw[d]);
    xs[d] = xn;
    __syncthreads();

    const float rot = (d < HD/2) ? -xs[d + HD/2] : xs[d - HD/2];
    const size_t csi = ((size_t)b * S + s) * HD + d;
    const float out = xn * cosp[csi] + rot * sinp[csi];

    if (slot < 8)
        g_q[(((size_t)b * H + slot) * S + s) * HD + d] = out;
    else
        g_k[(((size_t)b * HKV + (slot - 8)) * S + s) * HD + d] = out;
}

// ---------------- Flash attention (fp32, causal, tanh softcap) — unchanged ----------------
constexpr int PAD = 260;
constexpr int FLASH_SMEM = (3 * 32 * PAD + 32 * 33) * 4;

__global__ __launch_bounds__(256) void flash_kernel()
{
    extern __shared__ float smf[];
    float* Qs = smf;
    float* Ks = smf + 32 * PAD;
    float* Vs = smf + 2 * 32 * PAD;
    float* Ps = smf + 3 * 32 * PAD;

    const int qt = blockIdx.x;
    const int h  = blockIdx.y;
    const int b  = blockIdx.z;
    const int q0 = qt * 32;
    const int hk = h >> 1;

    const int tid = threadIdx.x;
    const int r = tid >> 3;
    const int g = tid & 7;

    const float* Qg = g_q + (((size_t)b * H   + h ) * S + q0) * HD;
    const float* Kg = g_k + (((size_t)b * HKV + hk) * S) * HD;
    const float* Vg = g_v + (((size_t)b * HKV + hk) * S) * HD;

    for (int i4 = tid; i4 < 32 * 64; i4 += 256) {
        int row = i4 >> 6, c4 = i4 & 63;
        *(float4*)(Qs + row * PAD + c4 * 4) = *(const float4*)(Qg + (size_t)row * HD + c4 * 4);
    }

    float4 o[8];
#pragma unroll
    for (int i = 0; i < 8; i++) o[i] = make_float4(0.f, 0.f, 0.f, 0.f);
    float m = -1e30f, l = 0.f;

    const int qg = q0 + r;

    for (int kt = 0; kt <= qt; kt++) {
        __syncthreads();
        const float* Kt = Kg + (size_t)kt * 32 * HD;
        const float* Vt = Vg + (size_t)kt * 32 * HD;
        for (int i4 = tid; i4 < 32 * 64; i4 += 256) {
            int row = i4 >> 6, c4 = i4 & 63;
            *(float4*)(Ks + row * PAD + c4 * 4) = *(const float4*)(Kt + (size_t)row * HD + c4 * 4);
            *(float4*)(Vs + row * PAD + c4 * 4) = *(const float4*)(Vt + (size_t)row * HD + c4 * 4);
        }
        __syncthreads();

        const float4* qrow = (const float4*)(Qs + r * PAD);
        const float4* k0p = (const float4*)(Ks + (g +  0) * PAD);
        const float4* k1p = (const float4*)(Ks + (g +  8) * PAD);
        const float4* k2p = (const float4*)(Ks + (g + 16) * PAD);
        const float4* k3p = (const float4*)(Ks + (g + 24) * PAD);
        float a0 = 0.f, a1 = 0.f, a2 = 0.f, a3 = 0.f;
#pragma unroll 4
        for (int d4 = 0; d4 < 64; d4++) {
            float4 q = qrow[d4];
            float4 kv;
            kv = k0p[d4]; a0 = fmaf(q.x,kv.x, fmaf(q.y,kv.y, fmaf(q.z,kv.z, fmaf(q.w,kv.w, a0))));
            kv = k1p[d4]; a1 = fmaf(q.x,kv.x, fmaf(q.y,kv.y, fmaf(q.z,kv.z, fmaf(q.w,kv.w, a1))));
            kv = k2p[d4]; a2 = fmaf(q.x,kv.x, fmaf(q.y,kv.y, fmaf(q.z,kv.z, fmaf(q.w,kv.w, a2))));
            kv = k3p[d4]; a3 = fmaf(q.x,kv.x, fmaf(q.y,kv.y, fmaf(q.z,kv.z, fmaf(q.w,kv.w, a3))));
        }
        float sc[4] = {a0, a1, a2, a3};
        float lm = -1e30f;
#pragma unroll
        for (int jj = 0; jj < 4; jj++) {
            float w = sc[jj] * SCALING;
            w = tanhf(w * (1.0f / SOFTCAP)) * SOFTCAP;
            int kg = kt * 32 + g + jj * 8;
            if (kg > qg) w = NEGBIG;
            sc[jj] = w;
            lm = fmaxf(lm, w);
        }
        lm = fmaxf(lm, __shfl_xor_sync(0xffffffffu, lm, 1));
        lm = fmaxf(lm, __shfl_xor_sync(0xffffffffu, lm, 2));
        lm = fmaxf(lm, __shfl_xor_sync(0xffffffffu, lm, 4));

        const float mn = fmaxf(m, lm);
        const float corr = __expf(m - mn);
        float psum = 0.f;
#pragma unroll
        for (int jj = 0; jj < 4; jj++) {
            float p = __expf(sc[jj] - mn);
            psum += p;
            Ps[r * 33 + g + jj * 8] = p;
        }
        psum += __shfl_xor_sync(0xffffffffu, psum, 1);
        psum += __shfl_xor_sync(0xffffffffu, psum, 2);
        psum += __shfl_xor_sync(0xffffffffu, psum, 4);
        l = l * corr + psum;
        m = mn;
#pragma unroll
        for (int i = 0; i < 8; i++) {
            o[i].x *= corr; o[i].y *= corr; o[i].z *= corr; o[i].w *= corr;
        }
        __syncwarp();

        const float* prow = Ps + r * 33;
        for (int j = 0; j < 32; j++) {
            const float p = prow[j];
            const float4* vrow = (const float4*)(Vs + j * PAD);
#pragma unroll
            for (int i = 0; i < 8; i++) {
                float4 vv = vrow[i * 8 + g];
                o[i].x = fmaf(p, vv.x, o[i].x);
                o[i].y = fmaf(p, vv.y, o[i].y);
                o[i].z = fmaf(p, vv.z, o[i].z);
                o[i].w = fmaf(p, vv.w, o[i].w);
            }
        }
    }

    const float inv = 1.0f / l;
    float* outp = g_attn + ((size_t)(b * S + q0 + r)) * (H * HD) + h * HD;
#pragma unroll
    for (int i = 0; i < 8; i++) {
        float4 v = o[i];
        v.x *= inv; v.y *= inv; v.z *= inv; v.w *= inv;
        *(float4*)(outp + (i * 8 + g) * 4) = v;
    }
}

// ---------------- Host launch ----------------
extern "C" void kernel_launch(void* const* d_in, const int* in_sizes, int n_in,
                              void* d_out, int out_size)
{
    const float* x    = (const float*)d_in[0];
    const float* cosp = (const float*)d_in[1];
    const float* sinp = (const float*)d_in[2];
    const float* q_w  = (const float*)d_in[4];
    const float* k_w  = (const float*)d_in[5];
    const float* v_w  = (const float*)d_in[6];
    const float* o_w  = (const float*)d_in[7];
    const float* qn_w = (const float*)d_in[8];
    const float* kn_w = (const float*)d_in[9];
    float* out = (float*)d_out;

    void *p_qkv, *p_attn, *p_xcat, *p_wqkvc, *p_acat, *p_woc;
    cudaGetSymbolAddress(&p_qkv,   g_qkv);
    cudaGetSymbolAddress(&p_attn,  g_attn);
    cudaGetSymbolAddress(&p_xcat,  g_xcat);
    cudaGetSymbolAddress(&p_wqkvc, g_wqkvc);
    cudaGetSymbolAddress(&p_acat,  g_acat);
    cudaGetSymbolAddress(&p_woc,   g_woc);
    float* qkv = (float*)p_qkv;
    float* attn = (float*)p_attn;
    __nv_bfloat16* xcat  = (__nv_bfloat16*)p_xcat;
    __nv_bfloat16* wqkvc = (__nv_bfloat16*)p_wqkvc;
    __nv_bfloat16* acat  = (__nv_bfloat16*)p_acat;
    __nv_bfloat16* woc   = (__nv_bfloat16*)p_woc;

    cudaFuncSetAttribute(flash_kernel, cudaFuncAttributeMaxDynamicSharedMemorySize, FLASH_SMEM);
    cudaFuncSetAttribute(gemm_bf16,  cudaFuncAttributeMaxDynamicSharedMemorySize, GEMM_SMEM);

    // 1) split-convert x and QKV weights
    {
        long tot = (long)NTOK * (K1 / 4);
        conv_cat<<<(unsigned)((tot + 255) / 256), 256>>>(x, xcat, K1, tot, 0);
        long totw = (long)QKV_COLS * (K1 / 4);
        conv_cat_qkv<<<(unsigned)((totw + 255) / 256), 256>>>(q_w, k_w, v_w, wqkvc);
    }
    // 2) QKV projection: [4096 x 4096] = xcat @ wqkvc^T  (bf16x3 HMMA)
    gemm_bf16<<<dim3(QKV_COLS / 128, NTOK / 128), 256, GEMM_SMEM>>>(xcat, wqkvc, qkv, K1C, QKV_COLS);

    // 3) RMSNorm + RoPE + transpose
    norm_rope_kernel<<<dim3(NTOK, 16), 256>>>(cosp, sinp, qn_w, kn_w);

    // 4) Flash attention
    flash_kernel<<<dim3(S / 32, H, B), 256, FLASH_SMEM>>>();

    // 5) split-convert attn output + O weights
    {
        long tot = (long)NTOK * (K2 / 4);
        conv_cat<<<(unsigned)((tot + 255) / 256), 256>>>(attn, acat, K2, tot, 0);
        long totw = (long)D * (K2 / 4);
        conv_cat<<<(unsigned)((totw + 255) / 256), 256>>>(o_w, woc, K2, totw, 1);
    }
    // 6) O projection: [4096 x 2560] = acat @ woc^T
    gemm_bf16<<<dim3(D / 128, NTOK / 128), 256, GEMM_SMEM>>>(acat, woc, out, K2C, D);
}

// round 9
// speedup vs baseline: 4.4047x; 4.1366x over previous
#include <cuda_runtime.h>
#include <cuda_bf16.h>
#include <math.h>
#include <cstdint>

// ---------------- Problem constants ----------------
constexpr int B   = 2;
constexpr int S   = 2048;
constexpr int D   = 2560;
constexpr int H   = 8;
constexpr int HKV = 4;
constexpr int HD  = 256;
constexpr int NTOK = B * S;                 // 4096
constexpr int QKV_COLS = H*HD + 2*HKV*HD;   // 4096
constexpr float EPS = 1e-6f;
constexpr float SCALING = 0.0625f;
constexpr float SOFTCAP = 4096.0f;
constexpr float NEGBIG = -1e9f;

constexpr int K1 = D;          // 2560, QKV reduction
constexpr int K1C = 3 * K1;    // 7680 cat
constexpr int K2 = H * HD;     // 2048, O-proj reduction
constexpr int K2C = 3 * K2;    // 6144 cat

// ---------------- Scratch (device globals) ----------------
__device__ float g_qkv[(size_t)NTOK * QKV_COLS];
__device__ __nv_bfloat16 g_xcat  [(size_t)NTOK * K1C];     // [hi|lo|hi]
__device__ __nv_bfloat16 g_wqkvc [(size_t)QKV_COLS * K1C]; // [hi|hi|lo]
__device__ __nv_bfloat16 g_acat  [(size_t)NTOK * K2C];     // [hi|lo|hi] (written by flash)
__device__ __nv_bfloat16 g_woc   [(size_t)D * K2C];        // [hi|hi|lo]
// split q/k/v for HMMA flash
__device__ __nv_bfloat16 g_qh[(size_t)B * H   * S * HD];
__device__ __nv_bfloat16 g_ql[(size_t)B * H   * S * HD];
__device__ __nv_bfloat16 g_kh[(size_t)B * HKV * S * HD];
__device__ __nv_bfloat16 g_kl[(size_t)B * HKV * S * HD];
__device__ __nv_bfloat16 g_vh[(size_t)B * HKV * S * HD];
__device__ __nv_bfloat16 g_vl[(size_t)B * HKV * S * HD];

// ================= helpers =================
__device__ __forceinline__ uint32_t smem_to_u32(const void* p) {
    uint32_t a;
    asm("{ .reg .u64 t; cvta.to.shared.u64 t, %1; cvt.u32.u64 %0, t; }" : "=r"(a) : "l"(p));
    return a;
}
#define SWZ128(o) ((o) ^ (((o) >> 3) & 0x70))

__device__ __forceinline__ void cp16(uint32_t s, const void* g) {
    asm volatile("cp.async.cg.shared.global [%0], [%1], 16;\n" :: "r"(s), "l"(g));
}
#define CP_COMMIT() asm volatile("cp.async.commit_group;\n" ::: "memory")
template<int N> __device__ __forceinline__ void cp_wait() {
    asm volatile("cp.async.wait_group %0;\n" :: "n"(N) : "memory");
}

__device__ __forceinline__ void ldm_x4(uint32_t* r, uint32_t addr) {
    asm volatile("ldmatrix.sync.aligned.m8n8.x4.shared.b16 {%0,%1,%2,%3}, [%4];"
        : "=r"(r[0]), "=r"(r[1]), "=r"(r[2]), "=r"(r[3]) : "r"(addr));
}
__device__ __forceinline__ void ldm_x4_t(uint32_t* r, uint32_t addr) {
    asm volatile("ldmatrix.sync.aligned.m8n8.x4.trans.shared.b16 {%0,%1,%2,%3}, [%4];"
        : "=r"(r[0]), "=r"(r[1]), "=r"(r[2]), "=r"(r[3]) : "r"(addr));
}
__device__ __forceinline__ void mma_bf16(float* d, const uint32_t* a, uint32_t b0, uint32_t b1) {
    asm volatile("mma.sync.aligned.m16n8k16.row.col.f32.bf16.bf16.f32 "
        "{%0,%1,%2,%3}, {%4,%5,%6,%7}, {%8,%9}, {%0,%1,%2,%3};"
        : "+f"(d[0]), "+f"(d[1]), "+f"(d[2]), "+f"(d[3])
        : "r"(a[0]), "r"(a[1]), "r"(a[2]), "r"(a[3]), "r"(b0), "r"(b1));
}
__device__ __forceinline__ uint32_t pack_bf16(float a, float b) {
    __nv_bfloat162 t = __floats2bfloat162_rn(a, b);
    return *(uint32_t*)&t;
}

// ================ Split-precision conversion kernels ================
__device__ __forceinline__ void split4(float4 v, __nv_bfloat16* h, __nv_bfloat16* l) {
    h[0] = __float2bfloat16(v.x); l[0] = __float2bfloat16(v.x - __bfloat162float(h[0]));
    h[1] = __float2bfloat16(v.y); l[1] = __float2bfloat16(v.y - __bfloat162float(h[1]));
    h[2] = __float2bfloat16(v.z); l[2] = __float2bfloat16(v.z - __bfloat162float(h[2]));
    h[3] = __float2bfloat16(v.w); l[3] = __float2bfloat16(v.w - __bfloat162float(h[3]));
}
__device__ __forceinline__ void st8(__nv_bfloat16* p, const __nv_bfloat16* v) {
    *(uint2*)p = *(const uint2*)v;
}

// mode 0 (activation): [hi | lo | hi]; mode 1 (weight): [hi | hi | lo]
__global__ __launch_bounds__(256) void conv_cat(const float* __restrict__ src,
                                                __nv_bfloat16* __restrict__ dst,
                                                int K, long tot, int mode)
{
    long idx = (long)blockIdx.x * 256 + threadIdx.x;
    if (idx >= tot) return;
    int kq = K >> 2;
    long r = idx / kq; int k4 = (int)(idx - r * kq);
    float4 v = ((const float4*)src)[idx];
    __nv_bfloat16 h[4], l[4];
    split4(v, h, l);
    __nv_bfloat16* row = dst + r * (long)(3 * K);
    st8(row + k4 * 4, h);
    st8(row + K + k4 * 4, mode ? h : l);
    st8(row + 2 * K + k4 * 4, mode ? l : h);
}

__global__ __launch_bounds__(256) void conv_cat_qkv(const float* __restrict__ qw,
                                                    const float* __restrict__ kw,
                                                    const float* __restrict__ vw,
                                                    __nv_bfloat16* __restrict__ dst)
{
    const int K = K1, kq = K >> 2;
    long idx = (long)blockIdx.x * 256 + threadIdx.x;
    long tot = (long)QKV_COLS * kq;
    if (idx >= tot) return;
    long r = idx / kq; int k4 = (int)(idx - r * kq);
    const float* src = (r < 2048) ? qw + r * (long)K
                     : (r < 3072) ? kw + (r - 2048) * (long)K
                                  : vw + (r - 3072) * (long)K;
    float4 v = ((const float4*)src)[k4];
    __nv_bfloat16 h[4], l[4];
    split4(v, h, l);
    __nv_bfloat16* row = dst + r * (long)(3 * K);
    st8(row + k4 * 4, h);
    st8(row + K + k4 * 4, h);     // weight: hi | hi | lo
    st8(row + 2 * K + k4 * 4, l);
}

// ================ bf16 HMMA GEMM (unchanged from R8) ================
constexpr int STAGE_BYTES = 32768;
constexpr int NSTAGE = 3;
constexpr int GEMM_SMEM = NSTAGE * STAGE_BYTES;

__device__ __forceinline__ void load_chunk(const char* Arow, const char* Brow, size_t rowbytes,
                                           uint32_t smem_base, int stage, long kbyte, int tid)
{
    uint32_t sa = smem_base + stage * STAGE_BYTES;
    uint32_t sb = sa + 16384;
#pragma unroll
    for (int p = 0; p < 4; p++) {
        int idx = p * 256 + tid;
        int row = idx >> 3, j = idx & 7;
        uint32_t off = (uint32_t)(row * 128 + j * 16);
        cp16(sa + SWZ128(off), Arow + (size_t)row * rowbytes + kbyte + j * 16);
    }
#pragma unroll
    for (int p = 0; p < 4; p++) {
        int idx = p * 256 + tid;
        int row = idx >> 3, j = idx & 7;
        uint32_t off = (uint32_t)(row * 128 + j * 16);
        cp16(sb + SWZ128(off), Brow + (size_t)row * rowbytes + kbyte + j * 16);
    }
    CP_COMMIT();
}

__global__ __launch_bounds__(256) void gemm_bf16(const __nv_bfloat16* __restrict__ A,
                                                 const __nv_bfloat16* __restrict__ Bw,
                                                 float* __restrict__ C,
                                                 int Kp, int Ntot)
{
    extern __shared__ char smem[];
    const uint32_t smem_base = smem_to_u32(smem);
    const int tid = threadIdx.x;
    const int wid = tid >> 5, lane = tid & 31;
    const int wm = wid & 1;
    const int wn = wid >> 1;
    const int n0 = blockIdx.x * 128;
    const int m0 = blockIdx.y * 128;

    const size_t rowbytes = (size_t)Kp * 2;
    const char* Arow = (const char*)A + (size_t)m0 * rowbytes;
    const char* Brow = (const char*)Bw + (size_t)n0 * rowbytes;
    const int C_chunks = Kp / 64;

    load_chunk(Arow, Brow, rowbytes, smem_base, 0, 0, tid);
    load_chunk(Arow, Brow, rowbytes, smem_base, 1, 128, tid);
    load_chunk(Arow, Brow, rowbytes, smem_base, 2, 256, tid);

    float acc[4][4][4];
#pragma unroll
    for (int i = 0; i < 4; i++)
#pragma unroll
        for (int j = 0; j < 4; j++)
#pragma unroll
            for (int q = 0; q < 4; q++) acc[i][j][q] = 0.f;

    const int a_row_l = (lane & 15);
    const int a_hi    = (lane >> 4) * 16;
    const int b_row_l = (lane & 7) + ((lane >> 4) & 1) * 8;
    const int b_hi    = ((lane >> 3) & 1) * 16;

    for (int c = 0; c < C_chunks; c++) {
        const int s = c % 3;
        if (c + 2 < C_chunks)      cp_wait<2>();
        else if (c + 1 < C_chunks) cp_wait<1>();
        else                       cp_wait<0>();
        __syncthreads();

        const uint32_t sa = smem_base + s * STAGE_BYTES;
        const uint32_t sb = sa + 16384;

#pragma unroll
        for (int ks = 0; ks < 4; ks++) {
            uint32_t a[4][4];
#pragma unroll
            for (int mf = 0; mf < 4; mf++) {
                int row = wm * 64 + mf * 16 + a_row_l;
                uint32_t kb = (uint32_t)(ks * 32 + a_hi) ^ ((uint32_t)(row & 7) << 4);
                ldm_x4(a[mf], sa + row * 128 + kb);
            }
            uint32_t bfr[2][4];
#pragma unroll
            for (int nb = 0; nb < 2; nb++) {
                int row = wn * 32 + nb * 16 + b_row_l;
                uint32_t kb = (uint32_t)(ks * 32 + b_hi) ^ ((uint32_t)(row & 7) << 4);
                ldm_x4(bfr[nb], sb + row * 128 + kb);
            }
#pragma unroll
            for (int mf = 0; mf < 4; mf++) {
#pragma unroll
                for (int nf = 0; nf < 4; nf++)
                    mma_bf16(acc[mf][nf], a[mf], bfr[nf >> 1][(nf & 1) * 2], bfr[nf >> 1][(nf & 1) * 2 + 1]);
            }
        }
        __syncthreads();
        if (c + 3 < C_chunks)
            load_chunk(Arow, Brow, rowbytes, smem_base, s, (long)(c + 3) * 128, tid);
    }

    const int er = lane >> 2;
    const int ec = (lane & 3) * 2;
#pragma unroll
    for (int mf = 0; mf < 4; mf++) {
        const int rbase = m0 + wm * 64 + mf * 16 + er;
#pragma unroll
        for (int nf = 0; nf < 4; nf++) {
            const int cbase = n0 + wn * 32 + nf * 8 + ec;
            float* p0 = C + (size_t)rbase * Ntot + cbase;
            float* p1 = C + (size_t)(rbase + 8) * Ntot + cbase;
            *(float2*)p0 = make_float2(acc[mf][nf][0], acc[mf][nf][1]);
            *(float2*)p1 = make_float2(acc[mf][nf][2], acc[mf][nf][3]);
        }
    }
}

// ---------------- RMSNorm + RoPE -> bf16 hi/lo split outputs ----------------
__global__ __launch_bounds__(256) void norm_rope_kernel(
    const float* __restrict__ cosp, const float* __restrict__ sinp,
    const float* __restrict__ qn_w, const float* __restrict__ kn_w)
{
    const int token = blockIdx.x;
    const int slot  = blockIdx.y;
    const int d     = threadIdx.x;
    const int b = token / S;
    const int s = token % S;

    const float* row = g_qkv + (size_t)token * QKV_COLS;
    float x;
    if (slot < 8)       x = row[slot * HD + d];
    else if (slot < 12) x = row[2048 + (slot - 8) * HD + d];
    else                x = row[3072 + (slot - 12) * HD + d];

    if (slot >= 12) {
        size_t o = (((size_t)b * HKV + (slot - 12)) * S + s) * HD + d;
        __nv_bfloat16 hb = __float2bfloat16(x);
        g_vh[o] = hb;
        g_vl[o] = __float2bfloat16(x - __bfloat162float(hb));
        return;
    }

    __shared__ float red[8];
    __shared__ float xs[HD];
    float ss = x * x;
#pragma unroll
    for (int o = 16; o > 0; o >>= 1) ss += __shfl_xor_sync(0xffffffffu, ss, o);
    if ((d & 31) == 0) red[d >> 5] = ss;
    __syncthreads();
    float tot = red[0];
#pragma unroll
    for (int i = 1; i < 8; i++) tot += red[i];
    const float scale = rsqrtf(tot * (1.0f / HD) + EPS);

    const float* nw = (slot < 8) ? qn_w : kn_w;
    const float xn = x * scale * (1.0f + nw[d]);
    xs[d] = xn;
    __syncthreads();

    const float rot = (d < HD/2) ? -xs[d + HD/2] : xs[d - HD/2];
    const size_t csi = ((size_t)b * S + s) * HD + d;
    const float out = xn * cosp[csi] + rot * sinp[csi];

    __nv_bfloat16 hb = __float2bfloat16(out);
    __nv_bfloat16 lb = __float2bfloat16(out - __bfloat162float(hb));
    if (slot < 8) {
        size_t o = (((size_t)b * H + slot) * S + s) * HD + d;
        g_qh[o] = hb; g_ql[o] = lb;
    } else {
        size_t o = (((size_t)b * HKV + (slot - 8)) * S + s) * HD + d;
        g_kh[o] = hb; g_kl[o] = lb;
    }
}

// ---------------- Flash attention: HMMA bf16 3-term split ----------------
// BM=64 q rows, BN=32 keys/tile, 128 threads (4 warps, each m16 x full N).
// smem: Qhi[64][256] | Qlo[64][256] | 2 stages of {Khi,Klo,Vhi,Vlo}[32][256].
// Row stride 512B with per-row XOR-16B swizzle; V read via ldmatrix.trans.
constexpr int FLASH2_SMEM = 196608;   // 64KB Q + 2*64KB stages

__global__ __launch_bounds__(128) void flash_mma()
{
    extern __shared__ char fsm[];
    const uint32_t sb0 = smem_to_u32(fsm);
    const uint32_t sQh = sb0, sQl = sb0 + 32768;

    const int qt = blockIdx.x;        // q tile (0..31), 64 rows each
    const int h  = blockIdx.y;
    const int b  = blockIdx.z;
    const int q0 = qt * 64;
    const int hk = h >> 1;            // GQA rep=2

    const int tid = threadIdx.x, warp = tid >> 5, lane = tid & 31;

    const __nv_bfloat16* Qhp = g_qh + (((size_t)b * H   + h ) * S + q0) * HD;
    const __nv_bfloat16* Qlp = g_ql + (((size_t)b * H   + h ) * S + q0) * HD;
    const __nv_bfloat16* Khp = g_kh + (((size_t)b * HKV + hk) * S) * HD;
    const __nv_bfloat16* Klp = g_kl + (((size_t)b * HKV + hk) * S) * HD;
    const __nv_bfloat16* Vhp = g_vh + (((size_t)b * HKV + hk) * S) * HD;
    const __nv_bfloat16* Vlp = g_vl + (((size_t)b * HKV + hk) * S) * HD;

    // Q load (group 0): 64 rows x 512B per part
    for (int u = tid; u < 2048; u += 128) {
        int row = u >> 5, c = u & 31;
        uint32_t off = (uint32_t)row * 512 + (((uint32_t)c * 16) ^ (((uint32_t)row & 7) << 4));
        cp16(sQh + off, Qhp + (size_t)row * HD + c * 8);
        cp16(sQl + off, Qlp + (size_t)row * HD + c * 8);
    }
    CP_COMMIT();

    const int ntiles = 2 * (qt + 1);

    // prefetch tiles 0,1
#pragma unroll 1
    for (int pt = 0; pt < 2; pt++) {
        uint32_t sB = sb0 + 65536 + pt * 65536;
        int j0 = pt * 32;
        for (int u = tid; u < 1024; u += 128) {
            int row = u >> 5, c = u & 31;
            uint32_t off = (uint32_t)row * 512 + (((uint32_t)c * 16) ^ (((uint32_t)row & 7) << 4));
            size_t g = (size_t)(j0 + row) * HD + c * 8;
            cp16(sB + off,         Khp + g);
            cp16(sB + 16384 + off, Klp + g);
            cp16(sB + 32768 + off, Vhp + g);
            cp16(sB + 49152 + off, Vlp + g);
        }
        CP_COMMIT();
    }

    float acc[32][4];
#pragma unroll
    for (int i = 0; i < 32; i++) { acc[i][0]=0.f; acc[i][1]=0.f; acc[i][2]=0.f; acc[i][3]=0.f; }
    float mrow0 = -1e30f, mrow1 = -1e30f, lrow0 = 0.f, lrow1 = 0.f;

    const int rA = q0 + warp * 16 + (lane >> 2);   // global q row for c0/c1

    // ldmatrix lane geometry (computed once)
    const int arow = warp * 16 + (lane & 15);
    const uint32_t aswz = ((uint32_t)(arow & 7)) << 4;
    const uint32_t asel = (uint32_t)(lane >> 4) * 16;
    const int brow = (lane & 7) + ((lane >> 4) & 1) * 8;
    const uint32_t bswz = ((uint32_t)(brow & 7)) << 4;
    const uint32_t bsel = (uint32_t)((lane >> 3) & 1) * 16;
    const int vlanerow = (lane & 7) + ((lane >> 3) & 1) * 8;
    const uint32_t vdsel = (uint32_t)((lane >> 4) & 1) * 16;

    for (int t = 0; t < ntiles; t++) {
        if (t + 1 < ntiles) cp_wait<1>(); else cp_wait<0>();
        __syncthreads();
        const uint32_t sK = sb0 + 65536 + (t & 1) * 65536;
        const uint32_t sV = sK + 32768;

        // ---- QK^T: scores m16 x n32, K=256, 3 split terms ----
        float sc[4][4];
#pragma unroll
        for (int i = 0; i < 4; i++) { sc[i][0]=0.f; sc[i][1]=0.f; sc[i][2]=0.f; sc[i][3]=0.f; }

#pragma unroll 4
        for (int kc = 0; kc < 16; kc++) {
            uint32_t kb_a = ((uint32_t)(kc * 32) + asel) ^ aswz;
            uint32_t aq[4], al[4];
            ldm_x4(aq, sQh + (uint32_t)arow * 512 + kb_a);
            ldm_x4(al, sQl + (uint32_t)arow * 512 + kb_a);
            uint32_t kb_b = ((uint32_t)(kc * 32) + bsel) ^ bswz;
            uint32_t bh0[4], bh1[4], bl0[4], bl1[4];
            ldm_x4(bh0, sK + (uint32_t)brow * 512 + kb_b);
            ldm_x4(bh1, sK + (uint32_t)(brow + 16) * 512 + kb_b);
            ldm_x4(bl0, sK + 16384 + (uint32_t)brow * 512 + kb_b);
            ldm_x4(bl1, sK + 16384 + (uint32_t)(brow + 16) * 512 + kb_b);

            mma_bf16(sc[0], aq, bh0[0], bh0[1]); mma_bf16(sc[0], al, bh0[0], bh0[1]); mma_bf16(sc[0], aq, bl0[0], bl0[1]);
            mma_bf16(sc[1], aq, bh0[2], bh0[3]); mma_bf16(sc[1], al, bh0[2], bh0[3]); mma_bf16(sc[1], aq, bl0[2], bl0[3]);
            mma_bf16(sc[2], aq, bh1[0], bh1[1]); mma_bf16(sc[2], al, bh1[0], bh1[1]); mma_bf16(sc[2], aq, bl1[0], bl1[1]);
            mma_bf16(sc[3], aq, bh1[2], bh1[3]); mma_bf16(sc[3], al, bh1[2], bh1[3]); mma_bf16(sc[3], aq, bl1[2], bl1[3]);
        }

        // ---- softcap + causal mask + online softmax ----
        const int j0 = t * 32;
        float mn0 = mrow0, mn1 = mrow1;
#pragma unroll
        for (int nf = 0; nf < 4; nf++) {
            const int cb = j0 + nf * 8 + (lane & 3) * 2;
#pragma unroll
            for (int e = 0; e < 4; e++) {
                float w = sc[nf][e] * SCALING;
                w = tanhf(w * (1.0f / SOFTCAP)) * SOFTCAP;
                const int col = cb + (e & 1);
                const int rowg = (e < 2) ? rA : (rA + 8);
                if (col > rowg) w = NEGBIG;
                sc[nf][e] = w;
                if (e < 2) mn0 = fmaxf(mn0, w); else mn1 = fmaxf(mn1, w);
            }
        }
        mn0 = fmaxf(mn0, __shfl_xor_sync(0xffffffffu, mn0, 1));
        mn0 = fmaxf(mn0, __shfl_xor_sync(0xffffffffu, mn0, 2));
        mn1 = fmaxf(mn1, __shfl_xor_sync(0xffffffffu, mn1, 1));
        mn1 = fmaxf(mn1, __shfl_xor_sync(0xffffffffu, mn1, 2));
        const float corr0 = __expf(mrow0 - mn0);
        const float corr1 = __expf(mrow1 - mn1);
        mrow0 = mn0; mrow1 = mn1;

        float ps0 = 0.f, ps1 = 0.f;
        uint32_t aphi[2][4], aplo[2][4];
#pragma unroll
        for (int f = 0; f < 2; f++) {
#pragma unroll
            for (int hf = 0; hf < 2; hf++) {
                const int nf = 2 * f + hf;
                float p00 = __expf(sc[nf][0] - mn0), p01 = __expf(sc[nf][1] - mn0);
                float p10 = __expf(sc[nf][2] - mn1), p11 = __expf(sc[nf][3] - mn1);
                ps0 += p00 + p01; ps1 += p10 + p11;
                float h00 = __bfloat162float(__float2bfloat16(p00));
                float h01 = __bfloat162float(__float2bfloat16(p01));
                float h10 = __bfloat162float(__float2bfloat16(p10));
                float h11 = __bfloat162float(__float2bfloat16(p11));
                aphi[f][hf * 2 + 0] = pack_bf16(h00, h01);
                aphi[f][hf * 2 + 1] = pack_bf16(h10, h11);
                aplo[f][hf * 2 + 0] = pack_bf16(p00 - h00, p01 - h01);
                aplo[f][hf * 2 + 1] = pack_bf16(p10 - h10, p11 - h11);
            }
        }
        ps0 += __shfl_xor_sync(0xffffffffu, ps0, 1);
        ps0 += __shfl_xor_sync(0xffffffffu, ps0, 2);
        ps1 += __shfl_xor_sync(0xffffffffu, ps1, 1);
        ps1 += __shfl_xor_sync(0xffffffffu, ps1, 2);
        lrow0 = lrow0 * corr0 + ps0;
        lrow1 = lrow1 * corr1 + ps1;

#pragma unroll
        for (int nf = 0; nf < 32; nf++) {
            acc[nf][0] *= corr0; acc[nf][1] *= corr0;
            acc[nf][2] *= corr1; acc[nf][3] *= corr1;
        }

        // ---- PV: A = p frags (regs), B = V via trans ldmatrix; 3 split terms ----
#pragma unroll
        for (int kf = 0; kf < 2; kf++) {
            const int jrow = kf * 16 + vlanerow;
            const uint32_t vbase = sV + (uint32_t)jrow * 512;
            const uint32_t vswz = ((uint32_t)(jrow & 7)) << 4;
#pragma unroll
            for (int g16 = 0; g16 < 16; g16++) {
                uint32_t dby = ((uint32_t)(g16 * 32) + vdsel) ^ vswz;
                uint32_t vhf[4], vlf[4];
                ldm_x4_t(vhf, vbase + dby);
                ldm_x4_t(vlf, vbase + 16384 + dby);
                mma_bf16(acc[2 * g16],     aphi[kf], vhf[0], vhf[1]);
                mma_bf16(acc[2 * g16],     aplo[kf], vhf[0], vhf[1]);
                mma_bf16(acc[2 * g16],     aphi[kf], vlf[0], vlf[1]);
                mma_bf16(acc[2 * g16 + 1], aphi[kf], vhf[2], vhf[3]);
                mma_bf16(acc[2 * g16 + 1], aplo[kf], vhf[2], vhf[3]);
                mma_bf16(acc[2 * g16 + 1], aphi[kf], vlf[2], vlf[3]);
            }
        }

        __syncthreads();
        if (t + 2 < ntiles) {
            uint32_t sB = sb0 + 65536 + (t & 1) * 65536;
            int j0n = (t + 2) * 32;
            for (int u = tid; u < 1024; u += 128) {
                int row = u >> 5, c = u & 31;
                uint32_t off = (uint32_t)row * 512 + (((uint32_t)c * 16) ^ (((uint32_t)row & 7) << 4));
                size_t g = (size_t)(j0n + row) * HD + c * 8;
                cp16(sB + off,         Khp + g);
                cp16(sB + 16384 + off, Klp + g);
                cp16(sB + 32768 + off, Vhp + g);
                cp16(sB + 49152 + off, Vlp + g);
            }
            CP_COMMIT();
        }
    }

    // ---- epilogue: normalize + split-write into g_acat [hi|lo|hi] ----
    const float inv0 = 1.0f / lrow0;
    const float inv1 = 1.0f / lrow1;
    const size_t tokA = (size_t)b * S + q0 + warp * 16 + (lane >> 2);
    __nv_bfloat16* rowA = g_acat + tokA * (size_t)K2C + h * HD;
    __nv_bfloat16* rowB = g_acat + (tokA + 8) * (size_t)K2C + h * HD;
#pragma unroll
    for (int nf = 0; nf < 32; nf++) {
        const int d = nf * 8 + (lane & 3) * 2;
        {
            float v0 = acc[nf][0] * inv0, v1 = acc[nf][1] * inv0;
            float h0 = __bfloat162float(__float2bfloat16(v0));
            float h1 = __bfloat162float(__float2bfloat16(v1));
            __nv_bfloat162 hp = __floats2bfloat162_rn(h0, h1);
            __nv_bfloat162 lp = __floats2bfloat162_rn(v0 - h0, v1 - h1);
            *(__nv_bfloat162*)(rowA + d)          = hp;
            *(__nv_bfloat162*)(rowA + K2 + d)     = lp;
            *(__nv_bfloat162*)(rowA + 2 * K2 + d) = hp;
        }
        {
            float v0 = acc[nf][2] * inv1, v1 = acc[nf][3] * inv1;
            float h0 = __bfloat162float(__float2bfloat16(v0));
            float h1 = __bfloat162float(__float2bfloat16(v1));
            __nv_bfloat162 hp = __floats2bfloat162_rn(h0, h1);
            __nv_bfloat162 lp = __floats2bfloat162_rn(v0 - h0, v1 - h1);
            *(__nv_bfloat162*)(rowB + d)          = hp;
            *(__nv_bfloat162*)(rowB + K2 + d)     = lp;
            *(__nv_bfloat162*)(rowB + 2 * K2 + d) = hp;
        }
    }
}

// ---------------- Host launch ----------------
extern "C" void kernel_launch(void* const* d_in, const int* in_sizes, int n_in,
                              void* d_out, int out_size)
{
    const float* x    = (const float*)d_in[0];
    const float* cosp = (const float*)d_in[1];
    const float* sinp = (const float*)d_in[2];
    const float* q_w  = (const float*)d_in[4];
    const float* k_w  = (const float*)d_in[5];
    const float* v_w  = (const float*)d_in[6];
    const float* o_w  = (const float*)d_in[7];
    const float* qn_w = (const float*)d_in[8];
    const float* kn_w = (const float*)d_in[9];
    float* out = (float*)d_out;

    void *p_qkv, *p_xcat, *p_wqkvc, *p_acat, *p_woc;
    cudaGetSymbolAddress(&p_qkv,   g_qkv);
    cudaGetSymbolAddress(&p_xcat,  g_xcat);
    cudaGetSymbolAddress(&p_wqkvc, g_wqkvc);
    cudaGetSymbolAddress(&p_acat,  g_acat);
    cudaGetSymbolAddress(&p_woc,   g_woc);
    float* qkv = (float*)p_qkv;
    __nv_bfloat16* xcat  = (__nv_bfloat16*)p_xcat;
    __nv_bfloat16* wqkvc = (__nv_bfloat16*)p_wqkvc;
    __nv_bfloat16* acat  = (__nv_bfloat16*)p_acat;
    __nv_bfloat16* woc   = (__nv_bfloat16*)p_woc;

    cudaFuncSetAttribute(gemm_bf16, cudaFuncAttributeMaxDynamicSharedMemorySize, GEMM_SMEM);
    cudaFuncSetAttribute(flash_mma, cudaFuncAttributeMaxDynamicSharedMemorySize, FLASH2_SMEM);

    // 1) split-convert x and QKV weights
    {
        long tot = (long)NTOK * (K1 / 4);
        conv_cat<<<(unsigned)((tot + 255) / 256), 256>>>(x, xcat, K1, tot, 0);
        long totw = (long)QKV_COLS * (K1 / 4);
        conv_cat_qkv<<<(unsigned)((totw + 255) / 256), 256>>>(q_w, k_w, v_w, wqkvc);
    }
    // 2) QKV projection (bf16x3 HMMA)
    gemm_bf16<<<dim3(QKV_COLS / 128, NTOK / 128), 256, GEMM_SMEM>>>(xcat, wqkvc, qkv, K1C, QKV_COLS);

    // 3) RMSNorm + RoPE + bf16 hi/lo split
    norm_rope_kernel<<<dim3(NTOK, 16), 256>>>(cosp, sinp, qn_w, kn_w);

    // 4) Flash attention (HMMA, writes g_acat directly)
    flash_mma<<<dim3(S / 64, H, B), 128, FLASH2_SMEM>>>();

    // 5) split-convert O weights (attn output already in acat form)
    {
        long totw = (long)D * (K2 / 4);
        conv_cat<<<(unsigned)((totw + 255) / 256), 256>>>(o_w, woc, K2, totw, 1);
    }
    // 6) O projection
    gemm_bf16<<<dim3(D / 128, NTOK / 128), 256, GEMM_SMEM>>>(acat, woc, out, K2C, D);
}